// round 1
// baseline (speedup 1.0000x reference)
#include <cuda_runtime.h>
#include <cuda_bf16.h>

// ---------------------------------------------------------------------------
// RGCN link predictor, restructured:
//   cnt/inv  -> GEMM1 (x @ [W1|root1]) -> scatter-mean -> (relu folded)
//            -> GEMM2 (relu(Z1) @ [W2|root2]) -> scatter-mean -> decoder MLP
// ---------------------------------------------------------------------------

#define NN   100000
#define REL  3
#define INC  128
#define HID  64
#define OUTC 32

// scratch (static device globals; no allocation allowed)
__device__ int   g_cnt[NN * REL];
__device__ float g_inv[NN * REL];
__device__ float g_H1[NN * 256];   // [W1_0|W1_1|W1_2|root1] outputs, 102.4 MB
__device__ float g_Z1[NN * 64];
__device__ float g_H2[NN * 128];   // [W2_0|W2_1|W2_2|root2] outputs
__device__ float g_Z2[NN * 32];
__device__ float g_Wc1[128 * 256];
__device__ float g_Wc2[64 * 128];

// ---------------------------------------------------------------------------
__global__ void zero_cnt_kernel(int n) {
    int i = blockIdx.x * blockDim.x + threadIdx.x;
    if (i < n) g_cnt[i] = 0;
}

__global__ void count_kernel(const int* __restrict__ dst,
                             const int* __restrict__ et, int E) {
    int e = blockIdx.x * blockDim.x + threadIdx.x;
    if (e < E) atomicAdd(&g_cnt[dst[e] * 3 + et[e]], 1);
}

__global__ void inv_kernel(int n) {
    int i = blockIdx.x * blockDim.x + threadIdx.x;
    if (i < n) g_inv[i] = 1.0f / fmaxf((float)g_cnt[i], 1.0f);
}

// pack [W1 r0|r1|r2 | root1] -> g_Wc1 [128,256]
__global__ void wc1_kernel(const float* __restrict__ W1,
                           const float* __restrict__ root1) {
    int i = blockIdx.x * blockDim.x + threadIdx.x;
    if (i < 128 * 256) {
        int k = i >> 8, c = i & 255;
        float v;
        if (c < 192) {
            int r = c >> 6, j = c & 63;
            v = W1[r * 128 * 64 + k * 64 + j];
        } else {
            v = root1[k * 64 + (c - 192)];
        }
        g_Wc1[i] = v;
    }
}

// pack [W2 r0|r1|r2 | root2] -> g_Wc2 [64,128]
__global__ void wc2_kernel(const float* __restrict__ W2,
                           const float* __restrict__ root2) {
    int i = blockIdx.x * blockDim.x + threadIdx.x;
    if (i < 64 * 128) {
        int k = i >> 7, c = i & 127;
        float v;
        if (c < 96) {
            int r = c >> 5, j = c & 31;
            v = W2[r * 64 * 32 + k * 32 + j];
        } else {
            v = root2[k * 32 + (c - 96)];
        }
        g_Wc2[i] = v;
    }
}

// ---------------------------------------------------------------------------
// simple fp32 SIMT GEMM: C[M,N] = op(A)[M,K] @ B[K,N], op = optional relu.
// block = 256 threads (16x16), tile 64x64, BK=16, 4x4 micro-tile per thread.
// ---------------------------------------------------------------------------
__device__ __forceinline__ void gemm_core(const float* __restrict__ A,
                                          const float* __restrict__ B,
                                          float* __restrict__ C,
                                          int M, int N, int K, bool reluA) {
    __shared__ float As[16][64];
    __shared__ float Bs[16][64];
    const int tid = threadIdx.x;
    const int tx = tid & 15, ty = tid >> 4;
    const int m0 = blockIdx.y * 64, n0 = blockIdx.x * 64;
    const int arow = tid >> 2, ac4 = tid & 3;   // A tile: 64 rows x 4 float4
    const int brow = tid >> 4, bc4 = tid & 15;  // B tile: 16 rows x 16 float4

    float acc[4][4] = {};

    for (int k0 = 0; k0 < K; k0 += 16) {
        float4 av = make_float4(0.f, 0.f, 0.f, 0.f);
        int gr = m0 + arow;
        if (gr < M) av = *(const float4*)&A[(size_t)gr * K + k0 + ac4 * 4];
        if (reluA) {
            av.x = fmaxf(av.x, 0.f); av.y = fmaxf(av.y, 0.f);
            av.z = fmaxf(av.z, 0.f); av.w = fmaxf(av.w, 0.f);
        }
        As[ac4 * 4 + 0][arow] = av.x;
        As[ac4 * 4 + 1][arow] = av.y;
        As[ac4 * 4 + 2][arow] = av.z;
        As[ac4 * 4 + 3][arow] = av.w;

        float4 bv = *(const float4*)&B[(size_t)(k0 + brow) * N + n0 + bc4 * 4];
        *(float4*)&Bs[brow][bc4 * 4] = bv;
        __syncthreads();

#pragma unroll
        for (int kk = 0; kk < 16; kk++) {
            float4 a = *(float4*)&As[kk][ty * 4];
            float4 b = *(float4*)&Bs[kk][tx * 4];
            acc[0][0] += a.x * b.x; acc[0][1] += a.x * b.y; acc[0][2] += a.x * b.z; acc[0][3] += a.x * b.w;
            acc[1][0] += a.y * b.x; acc[1][1] += a.y * b.y; acc[1][2] += a.y * b.z; acc[1][3] += a.y * b.w;
            acc[2][0] += a.z * b.x; acc[2][1] += a.z * b.y; acc[2][2] += a.z * b.z; acc[2][3] += a.z * b.w;
            acc[3][0] += a.w * b.x; acc[3][1] += a.w * b.y; acc[3][2] += a.w * b.z; acc[3][3] += a.w * b.w;
        }
        __syncthreads();
    }

#pragma unroll
    for (int i = 0; i < 4; i++) {
        int gr = m0 + ty * 4 + i;
        if (gr < M) {
            float4 v = make_float4(acc[i][0], acc[i][1], acc[i][2], acc[i][3]);
            *(float4*)&C[(size_t)gr * N + n0 + tx * 4] = v;
        }
    }
}

__global__ void gemm1_kernel(const float* __restrict__ x) {
    gemm_core(x, g_Wc1, g_H1, NN, 256, 128, false);
}
__global__ void gemm2_kernel() {
    gemm_core(g_Z1, g_Wc2, g_H2, NN, 128, 64, true);
}

// ---------------------------------------------------------------------------
__global__ void initz1_kernel(const float* __restrict__ b1) {
    int i = blockIdx.x * blockDim.x + threadIdx.x;
    if (i < NN * 64) {
        int j = i & 63;
        g_Z1[i] = g_H1[(size_t)(i >> 6) * 256 + 192 + j] + b1[j];
    }
}
__global__ void initz2_kernel(const float* __restrict__ b2) {
    int i = blockIdx.x * blockDim.x + threadIdx.x;
    if (i < NN * 32) {
        int j = i & 31;
        g_Z2[i] = g_H2[(size_t)(i >> 5) * 128 + 96 + j] + b2[j];
    }
}

// ---------------------------------------------------------------------------
// scatter-mean: out[dst, :] += H[src, r*C : r*C+C] * inv[dst][r]
// C/4 threads per edge; float4 gather + 4 scalar float atomics per thread.
// ---------------------------------------------------------------------------
template <int C, int HS>
__device__ __forceinline__ void agg_core(const float* __restrict__ H,
                                         float* __restrict__ out,
                                         const int* __restrict__ src,
                                         const int* __restrict__ dst,
                                         const int* __restrict__ et, int E) {
    const int CH = C / 4;
    int t = blockIdx.x * blockDim.x + threadIdx.x;
    int e = t / CH;
    int c = t - e * CH;
    if (e >= E) return;
    int s = src[e], d = dst[e], r = et[e];
    float sc = g_inv[d * 3 + r];
    float4 v = *(const float4*)&H[(size_t)s * HS + r * C + c * 4];
    float* o = &out[(size_t)d * C + c * 4];
    atomicAdd(o + 0, v.x * sc);
    atomicAdd(o + 1, v.y * sc);
    atomicAdd(o + 2, v.z * sc);
    atomicAdd(o + 3, v.w * sc);
}

__global__ void agg1_kernel(const int* __restrict__ src, const int* __restrict__ dst,
                            const int* __restrict__ et, int E) {
    agg_core<64, 256>(g_H1, g_Z1, src, dst, et, E);
}
__global__ void agg2_kernel(const int* __restrict__ src, const int* __restrict__ dst,
                            const int* __restrict__ et, int E) {
    agg_core<32, 128>(g_H2, g_Z2, src, dst, et, E);
}

// ---------------------------------------------------------------------------
// decoder: out[p] = relu(concat(z2[s], z2[d]) @ Wd1 + bd1) @ Wd2 + bd2
// one thread per pred edge; Wd1/bd1/Wd2 staged in SMEM; 4-wide j blocking.
// ---------------------------------------------------------------------------
__global__ void __launch_bounds__(128) decoder_kernel(
    const int* __restrict__ psrc, const int* __restrict__ pdst,
    const float* __restrict__ Wd1, const float* __restrict__ bd1,
    const float* __restrict__ Wd2, const float* __restrict__ bd2,
    float* __restrict__ out, int P) {
    __shared__ float sW[64 * 64];
    __shared__ float sB1[64];
    __shared__ float sW2[64];
    int tid = threadIdx.x;
    for (int i = tid; i < 64 * 64; i += 128) sW[i] = Wd1[i];
    if (tid < 64) { sB1[tid] = bd1[tid]; sW2[tid] = Wd2[tid]; }
    __syncthreads();

    int p = blockIdx.x * 128 + tid;
    if (p >= P) return;
    int s = psrc[p], d = pdst[p];

    float ef[64];
#pragma unroll
    for (int q = 0; q < 8; q++) {
        float4 v = *(const float4*)&g_Z2[(size_t)s * 32 + q * 4];
        ef[q * 4 + 0] = v.x; ef[q * 4 + 1] = v.y;
        ef[q * 4 + 2] = v.z; ef[q * 4 + 3] = v.w;
    }
#pragma unroll
    for (int q = 0; q < 8; q++) {
        float4 v = *(const float4*)&g_Z2[(size_t)d * 32 + q * 4];
        ef[32 + q * 4 + 0] = v.x; ef[32 + q * 4 + 1] = v.y;
        ef[32 + q * 4 + 2] = v.z; ef[32 + q * 4 + 3] = v.w;
    }

    float o = bd2[0];
    for (int j0 = 0; j0 < 64; j0 += 4) {
        float4 bb = *(float4*)&sB1[j0];
        float a0 = bb.x, a1 = bb.y, a2 = bb.z, a3 = bb.w;
#pragma unroll
        for (int k = 0; k < 64; k++) {
            float4 w = *(float4*)&sW[k * 64 + j0];
            float ev = ef[k];
            a0 += ev * w.x; a1 += ev * w.y; a2 += ev * w.z; a3 += ev * w.w;
        }
        float4 w2 = *(float4*)&sW2[j0];
        o += fmaxf(a0, 0.f) * w2.x + fmaxf(a1, 0.f) * w2.y +
             fmaxf(a2, 0.f) * w2.z + fmaxf(a3, 0.f) * w2.w;
    }
    out[p] = o;
}

// ---------------------------------------------------------------------------
extern "C" void kernel_launch(void* const* d_in, const int* in_sizes, int n_in,
                              void* d_out, int out_size) {
    const float* x     = (const float*)d_in[0];
    const int*   ei    = (const int*)d_in[1];
    const int*   et    = (const int*)d_in[2];
    const int*   pe    = (const int*)d_in[3];
    const float* W1    = (const float*)d_in[4];
    const float* root1 = (const float*)d_in[5];
    const float* b1    = (const float*)d_in[6];
    const float* W2    = (const float*)d_in[7];
    const float* root2 = (const float*)d_in[8];
    const float* b2    = (const float*)d_in[9];
    const float* Wd1   = (const float*)d_in[10];
    const float* bd1   = (const float*)d_in[11];
    const float* Wd2   = (const float*)d_in[12];
    const float* bd2   = (const float*)d_in[13];
    float* out = (float*)d_out;

    const int E = in_sizes[1] / 2;
    const int P = in_sizes[3] / 2;
    const int* src = ei;
    const int* dst = ei + E;
    const int* ps  = pe;
    const int* pd  = pe + P;

    // counts + inverse means (shared by both layers)
    zero_cnt_kernel<<<(NN * 3 + 255) / 256, 256>>>(NN * 3);
    count_kernel<<<(E + 255) / 256, 256>>>(dst, et, E);
    inv_kernel<<<(NN * 3 + 255) / 256, 256>>>(NN * 3);

    // pack weights
    wc1_kernel<<<(128 * 256 + 255) / 256, 256>>>(W1, root1);
    wc2_kernel<<<(64 * 128 + 255) / 256, 256>>>(W2, root2);

    // layer 1
    {
        dim3 g(256 / 64, (NN + 63) / 64);
        gemm1_kernel<<<g, 256>>>(x);
    }
    initz1_kernel<<<(NN * 64 + 255) / 256, 256>>>(b1);
    {
        long long t = (long long)E * 16;
        agg1_kernel<<<(unsigned)((t + 255) / 256), 256>>>(src, dst, et, E);
    }

    // layer 2 (relu folded into GEMM2 A-loads)
    {
        dim3 g(128 / 64, (NN + 63) / 64);
        gemm2_kernel<<<g, 256>>>();
    }
    initz2_kernel<<<(NN * 32 + 255) / 256, 256>>>(b2);
    {
        long long t = (long long)E * 8;
        agg2_kernel<<<(unsigned)((t + 255) / 256), 256>>>(src, dst, et, E);
    }

    // decoder
    decoder_kernel<<<(P + 127) / 128, 128>>>(ps, pd, Wd1, bd1, Wd2, bd2, out, P);
}

// round 4
// speedup vs baseline: 1.0065x; 1.0065x over previous
#include <cuda_runtime.h>
#include <cuda_bf16.h>

// ---------------------------------------------------------------------------
// RGCN link predictor:
//   cnt/inv -> GEMM1 (x @ [W1|root1], fused epilogue -> H1/Z1) -> scatter
//           -> GEMM2 (relu(Z1) @ [W2|root2], fused -> H2/Z2)   -> scatter
//           -> decoder MLP
// NOTE: __device__ globals are only ever referenced from device code
// (host-side kernel args of __device__ arrays resolve to the host shadow
// symbol -> garbage pointer; that was the round-2/3 failure).
// ---------------------------------------------------------------------------

#define NN   100000
#define REL  3

// scratch (static device globals; no allocation allowed)
__device__ int   g_cnt[NN * REL];
__device__ float g_inv[NN * REL];
__device__ float g_H1[NN * 192];   // message part of layer-1 transform
__device__ float g_Z1[NN * 64];
__device__ float g_H2[NN * 96];    // message part of layer-2 transform
__device__ float g_Z2[NN * 32];
__device__ float g_Wc1[128 * 256];
__device__ float g_Wc2[64 * 128];

// ---------------------------------------------------------------------------
__global__ void zero_cnt_kernel(int n) {
    int i = blockIdx.x * blockDim.x + threadIdx.x;
    if (i < n) g_cnt[i] = 0;
}

__global__ void count_kernel(const int* __restrict__ dst,
                             const int* __restrict__ et, int E) {
    int e = blockIdx.x * blockDim.x + threadIdx.x;
    if (e < E) atomicAdd(&g_cnt[dst[e] * 3 + et[e]], 1);
}

__global__ void inv_kernel(int n) {
    int i = blockIdx.x * blockDim.x + threadIdx.x;
    if (i < n) g_inv[i] = 1.0f / fmaxf((float)g_cnt[i], 1.0f);
}

// pack [W1 r0|r1|r2 | root1] -> g_Wc1 [128,256]
__global__ void wc1_kernel(const float* __restrict__ W1,
                           const float* __restrict__ root1) {
    int i = blockIdx.x * blockDim.x + threadIdx.x;
    if (i < 128 * 256) {
        int k = i >> 8, c = i & 255;
        float v;
        if (c < 192) {
            int r = c >> 6, j = c & 63;
            v = W1[r * 128 * 64 + k * 64 + j];
        } else {
            v = root1[k * 64 + (c - 192)];
        }
        g_Wc1[i] = v;
    }
}

// pack [W2 r0|r1|r2 | root2] -> g_Wc2 [64,128]
__global__ void wc2_kernel(const float* __restrict__ W2,
                           const float* __restrict__ root2) {
    int i = blockIdx.x * blockDim.x + threadIdx.x;
    if (i < 64 * 128) {
        int k = i >> 7, c = i & 127;
        float v;
        if (c < 96) {
            int r = c >> 5, j = c & 31;
            v = W2[r * 64 * 32 + k * 32 + j];
        } else {
            v = root2[k * 32 + (c - 96)];
        }
        g_Wc2[i] = v;
    }
}

// ---------------------------------------------------------------------------
// 128x128 tile fp32 GEMM, BK=16, 256 threads, 8x8 microtile, double-buffered.
// Fused epilogue: output cols [0,HCOLS) -> H (row stride HCOLS),
//                 cols [HCOLS,NTOT)     -> Z (row stride NTOT-HCOLS) + bias.
// RELU applies relu to A elements on load.  __device__ core: all pointers are
// bound in device code by the wrapper kernels.
// ---------------------------------------------------------------------------
template <int NTOT, int K, int HCOLS, bool RELU>
__device__ __forceinline__ void gemm_fused_core(
    const float* __restrict__ A, const float* __restrict__ B,
    float* __restrict__ H, float* __restrict__ Z,
    const float* __restrict__ bias, int M) {

    __shared__ float As[2][16][128];
    __shared__ float Bs[2][16][128];

    const int tid = threadIdx.x;
    const int tx = tid & 15, ty = tid >> 4;
    const int m0 = blockIdx.y * 128, n0 = blockIdx.x * 128;

    float4 aReg[2], bReg[2];
    float acc[8][8] = {};

    auto loadTiles = [&](int k0) {
#pragma unroll
        for (int i = 0; i < 2; i++) {
            int idx = tid + i * 256;
            int row = idx >> 2, c4 = idx & 3;
            int gr = m0 + row;
            float4 v = make_float4(0.f, 0.f, 0.f, 0.f);
            if (gr < M) v = *(const float4*)&A[(size_t)gr * K + k0 + c4 * 4];
            if (RELU) {
                v.x = fmaxf(v.x, 0.f); v.y = fmaxf(v.y, 0.f);
                v.z = fmaxf(v.z, 0.f); v.w = fmaxf(v.w, 0.f);
            }
            aReg[i] = v;
        }
#pragma unroll
        for (int i = 0; i < 2; i++) {
            int idx = tid + i * 256;
            int row = idx >> 5, c4 = idx & 31;
            bReg[i] = *(const float4*)&B[(size_t)(k0 + row) * NTOT + n0 + c4 * 4];
        }
    };
    auto storeTiles = [&](int buf) {
#pragma unroll
        for (int i = 0; i < 2; i++) {
            int idx = tid + i * 256;
            int row = idx >> 2, c4 = idx & 3;
            As[buf][c4 * 4 + 0][row] = aReg[i].x;
            As[buf][c4 * 4 + 1][row] = aReg[i].y;
            As[buf][c4 * 4 + 2][row] = aReg[i].z;
            As[buf][c4 * 4 + 3][row] = aReg[i].w;
        }
#pragma unroll
        for (int i = 0; i < 2; i++) {
            int idx = tid + i * 256;
            int row = idx >> 5, c4 = idx & 31;
            *(float4*)&Bs[buf][row][c4 * 4] = bReg[i];
        }
    };

    constexpr int KT = K / 16;
    loadTiles(0);
    storeTiles(0);
    __syncthreads();

    int buf = 0;
#pragma unroll
    for (int kt = 0; kt < KT; kt++) {
        if (kt + 1 < KT) loadTiles((kt + 1) * 16);

#pragma unroll
        for (int kk = 0; kk < 16; kk++) {
            float4 a0 = *(float4*)&As[buf][kk][ty * 8];
            float4 a1 = *(float4*)&As[buf][kk][ty * 8 + 4];
            float4 b0 = *(float4*)&Bs[buf][kk][tx * 8];
            float4 b1 = *(float4*)&Bs[buf][kk][tx * 8 + 4];
            float av[8] = {a0.x, a0.y, a0.z, a0.w, a1.x, a1.y, a1.z, a1.w};
            float bv[8] = {b0.x, b0.y, b0.z, b0.w, b1.x, b1.y, b1.z, b1.w};
#pragma unroll
            for (int i = 0; i < 8; i++)
#pragma unroll
                for (int j = 0; j < 8; j++)
                    acc[i][j] += av[i] * bv[j];
        }

        if (kt + 1 < KT) {
            buf ^= 1;
            storeTiles(buf);
            __syncthreads();
        }
    }

    const int cb = n0 + tx * 8;
    constexpr int ZW = NTOT - HCOLS;
    if (cb < HCOLS) {
#pragma unroll
        for (int i = 0; i < 8; i++) {
            int gr = m0 + ty * 8 + i;
            if (gr < M) {
                *(float4*)&H[(size_t)gr * HCOLS + cb] =
                    make_float4(acc[i][0], acc[i][1], acc[i][2], acc[i][3]);
                *(float4*)&H[(size_t)gr * HCOLS + cb + 4] =
                    make_float4(acc[i][4], acc[i][5], acc[i][6], acc[i][7]);
            }
        }
    } else {
        int zc = cb - HCOLS;
        float4 bia0 = *(const float4*)&bias[zc];
        float4 bia1 = *(const float4*)&bias[zc + 4];
#pragma unroll
        for (int i = 0; i < 8; i++) {
            int gr = m0 + ty * 8 + i;
            if (gr < M) {
                *(float4*)&Z[(size_t)gr * ZW + zc] =
                    make_float4(acc[i][0] + bia0.x, acc[i][1] + bia0.y,
                                acc[i][2] + bia0.z, acc[i][3] + bia0.w);
                *(float4*)&Z[(size_t)gr * ZW + zc + 4] =
                    make_float4(acc[i][4] + bia1.x, acc[i][5] + bia1.y,
                                acc[i][6] + bia1.z, acc[i][7] + bia1.w);
            }
        }
    }
}

// wrappers: bind __device__ globals in device code
__global__ void __launch_bounds__(256) gemm1_kernel(const float* __restrict__ x,
                                                    const float* __restrict__ b1) {
    gemm_fused_core<256, 128, 192, false>(x, g_Wc1, g_H1, g_Z1, b1, NN);
}
__global__ void __launch_bounds__(256) gemm2_kernel(const float* __restrict__ b2) {
    gemm_fused_core<128, 64, 96, true>(g_Z1, g_Wc2, g_H2, g_Z2, b2, NN);
}

// ---------------------------------------------------------------------------
// scatter-mean: out[dst, :] += H[src, r*C : r*C+C] * inv[dst][r]
// C/4 threads per edge; float4 gather + 4 scalar float atomics (RED).
// ---------------------------------------------------------------------------
template <int C, int HS>
__device__ __forceinline__ void agg_core(const float* __restrict__ H,
                                         float* __restrict__ out,
                                         const int* __restrict__ src,
                                         const int* __restrict__ dst,
                                         const int* __restrict__ et, int E) {
    const int CH = C / 4;
    int t = blockIdx.x * blockDim.x + threadIdx.x;
    int e = t / CH;
    int c = t - e * CH;
    if (e >= E) return;
    int s = src[e], d = dst[e], r = et[e];
    float sc = g_inv[d * 3 + r];
    float4 v = *(const float4*)&H[(size_t)s * HS + r * C + c * 4];
    float* o = &out[(size_t)d * C + c * 4];
    atomicAdd(o + 0, v.x * sc);
    atomicAdd(o + 1, v.y * sc);
    atomicAdd(o + 2, v.z * sc);
    atomicAdd(o + 3, v.w * sc);
}

__global__ void agg1_kernel(const int* __restrict__ src, const int* __restrict__ dst,
                            const int* __restrict__ et, int E) {
    agg_core<64, 192>(g_H1, g_Z1, src, dst, et, E);
}
__global__ void agg2_kernel(const int* __restrict__ src, const int* __restrict__ dst,
                            const int* __restrict__ et, int E) {
    agg_core<32, 96>(g_H2, g_Z2, src, dst, et, E);
}

// ---------------------------------------------------------------------------
// decoder: out[p] = relu(concat(z2[s], z2[d]) @ Wd1 + bd1) @ Wd2 + bd2
// ---------------------------------------------------------------------------
__global__ void __launch_bounds__(128) decoder_kernel(
    const int* __restrict__ psrc, const int* __restrict__ pdst,
    const float* __restrict__ Wd1, const float* __restrict__ bd1,
    const float* __restrict__ Wd2, const float* __restrict__ bd2,
    float* __restrict__ out, int P) {
    __shared__ float sW[64 * 64];
    __shared__ float sB1[64];
    __shared__ float sW2[64];
    int tid = threadIdx.x;
    for (int i = tid; i < 64 * 64; i += 128) sW[i] = Wd1[i];
    if (tid < 64) { sB1[tid] = bd1[tid]; sW2[tid] = Wd2[tid]; }
    __syncthreads();

    int p = blockIdx.x * 128 + tid;
    if (p >= P) return;
    int s = psrc[p], d = pdst[p];

    float ef[64];
#pragma unroll
    for (int q = 0; q < 8; q++) {
        float4 v = *(const float4*)&g_Z2[(size_t)s * 32 + q * 4];
        ef[q * 4 + 0] = v.x; ef[q * 4 + 1] = v.y;
        ef[q * 4 + 2] = v.z; ef[q * 4 + 3] = v.w;
    }
#pragma unroll
    for (int q = 0; q < 8; q++) {
        float4 v = *(const float4*)&g_Z2[(size_t)d * 32 + q * 4];
        ef[32 + q * 4 + 0] = v.x; ef[32 + q * 4 + 1] = v.y;
        ef[32 + q * 4 + 2] = v.z; ef[32 + q * 4 + 3] = v.w;
    }

    float o = bd2[0];
    for (int j0 = 0; j0 < 64; j0 += 4) {
        float4 bb = *(float4*)&sB1[j0];
        float a0 = bb.x, a1 = bb.y, a2 = bb.z, a3 = bb.w;
#pragma unroll
        for (int k = 0; k < 64; k++) {
            float4 w = *(float4*)&sW[k * 64 + j0];
            float ev = ef[k];
            a0 += ev * w.x; a1 += ev * w.y; a2 += ev * w.z; a3 += ev * w.w;
        }
        float4 w2 = *(float4*)&sW2[j0];
        o += fmaxf(a0, 0.f) * w2.x + fmaxf(a1, 0.f) * w2.y +
             fmaxf(a2, 0.f) * w2.z + fmaxf(a3, 0.f) * w2.w;
    }
    out[p] = o;
}

// ---------------------------------------------------------------------------
extern "C" void kernel_launch(void* const* d_in, const int* in_sizes, int n_in,
                              void* d_out, int out_size) {
    const float* x     = (const float*)d_in[0];
    const int*   ei    = (const int*)d_in[1];
    const int*   et    = (const int*)d_in[2];
    const int*   pe    = (const int*)d_in[3];
    const float* W1    = (const float*)d_in[4];
    const float* root1 = (const float*)d_in[5];
    const float* b1    = (const float*)d_in[6];
    const float* W2    = (const float*)d_in[7];
    const float* root2 = (const float*)d_in[8];
    const float* b2    = (const float*)d_in[9];
    const float* Wd1   = (const float*)d_in[10];
    const float* bd1   = (const float*)d_in[11];
    const float* Wd2   = (const float*)d_in[12];
    const float* bd2   = (const float*)d_in[13];
    float* out = (float*)d_out;

    const int E = in_sizes[1] / 2;
    const int P = in_sizes[3] / 2;
    const int* src = ei;
    const int* dst = ei + E;
    const int* ps  = pe;
    const int* pd  = pe + P;

    // counts + inverse means (shared by both layers)
    zero_cnt_kernel<<<(NN * 3 + 255) / 256, 256>>>(NN * 3);
    count_kernel<<<(E + 255) / 256, 256>>>(dst, et, E);
    inv_kernel<<<(NN * 3 + 255) / 256, 256>>>(NN * 3);

    // pack weights
    wc1_kernel<<<(128 * 256 + 255) / 256, 256>>>(W1, root1);
    wc2_kernel<<<(64 * 128 + 255) / 256, 256>>>(W2, root2);

    // layer 1: GEMM (fused root+bias -> Z1, messages -> H1), then scatter
    {
        dim3 g(2, (NN + 127) / 128);
        gemm1_kernel<<<g, 256>>>(x, b1);
    }
    {
        long long t = (long long)E * 16;
        agg1_kernel<<<(unsigned)((t + 255) / 256), 256>>>(src, dst, et, E);
    }

    // layer 2 (relu folded into GEMM2 A-loads)
    {
        dim3 g(1, (NN + 127) / 128);
        gemm2_kernel<<<g, 256>>>(b2);
    }
    {
        long long t = (long long)E * 8;
        agg2_kernel<<<(unsigned)((t + 255) / 256), 256>>>(src, dst, et, E);
    }

    // decoder
    decoder_kernel<<<(P + 127) / 128, 128>>>(ps, pd, Wd1, bd1, Wd2, bd2, out, P);
}